// round 2
// baseline (speedup 1.0000x reference)
#include <cuda_runtime.h>
#include <cuda_bf16.h>
#include <cstdint>

// AtomTypeLinear: out[n,:] = x[n,:] @ M[type[n]] + b[type[n]]
// N=100000, IN=OUT=64, NUM_TYPES=64, fp32.
//
// Counting-sort rows by type, then per-type GEMM tiles with
// mma.sync.m16n8k8 tf32 (W staged in smem, rows gathered/scattered).
// types dtype (int32 vs int64) is detected at runtime.

#define NUM_TYPES 64
#define MAX_N     102400

__device__ int g_counts[NUM_TYPES];
__device__ int g_offsets[NUM_TYPES + 1];
__device__ int g_cursor[NUM_TYPES];
__device__ int g_perm[MAX_N];
__device__ int g_is64;

// ---------------------------------------------------------------------------
// dtype detection: values are in [0,64). If stored as int64 (LE), every odd
// 32-bit word is zero. As int32 random values, P(64 odd words all zero) ~ 0.
// Reads only the first 512 bytes -> safe under either interpretation.
// ---------------------------------------------------------------------------
__global__ void k_detect(const int* __restrict__ t32, int n) {
    int words = n < 128 ? n : 128;
    int is64 = 1;
    for (int i = 1; i < words; i += 2)
        if (t32[i] != 0) { is64 = 0; break; }
    g_is64 = is64;
}

__device__ __forceinline__ int get_type(const void* types, int i, int is64) {
    int t = is64 ? (int)((const long long*)types)[i]
                 : ((const int*)types)[i];
    // guard: wrong dtype guess fails on rel_err, not on an IMA
    return (t >= 0 && t < NUM_TYPES) ? t : 0;
}

// ---------------------------------------------------------------------------
// tf32 helpers
// ---------------------------------------------------------------------------
__device__ __forceinline__ uint32_t f2tf32(float f) {
    uint32_t r;
    asm("cvt.rna.tf32.f32 %0, %1;" : "=r"(r) : "f"(f));
    return r;
}

__device__ __forceinline__ void mma_tf32(float* c, const uint32_t* a,
                                         uint32_t b0, uint32_t b1) {
    asm volatile(
        "mma.sync.aligned.m16n8k8.row.col.f32.tf32.tf32.f32 "
        "{%0,%1,%2,%3}, {%4,%5,%6,%7}, {%8,%9}, {%0,%1,%2,%3};"
        : "+f"(c[0]), "+f"(c[1]), "+f"(c[2]), "+f"(c[3])
        : "r"(a[0]), "r"(a[1]), "r"(a[2]), "r"(a[3]), "r"(b0), "r"(b1));
}

// ---------------------------------------------------------------------------
// Pass 1: counting sort of row indices by type
// ---------------------------------------------------------------------------
__global__ void k_zero() {
    int t = threadIdx.x;
    if (t < NUM_TYPES) g_counts[t] = 0;
}

__global__ void k_hist(const void* __restrict__ types, int n) {
    __shared__ int sh[NUM_TYPES];
    if (threadIdx.x < NUM_TYPES) sh[threadIdx.x] = 0;
    __syncthreads();
    const int is64 = g_is64;
    for (int i = blockIdx.x * blockDim.x + threadIdx.x; i < n;
         i += gridDim.x * blockDim.x) {
        atomicAdd(&sh[get_type(types, i, is64)], 1);
    }
    __syncthreads();
    if (threadIdx.x < NUM_TYPES)
        atomicAdd(&g_counts[threadIdx.x], sh[threadIdx.x]);
}

__global__ void k_scan(int n) {
    __shared__ int sh[NUM_TYPES];
    int t = threadIdx.x;
    if (t < NUM_TYPES) sh[t] = g_counts[t];
    __syncthreads();
    if (t == 0) {
        int acc = 0;
        for (int i = 0; i < NUM_TYPES; i++) {
            int c = sh[i];
            sh[i] = acc;
            acc += c;
        }
    }
    __syncthreads();
    if (t < NUM_TYPES) {
        g_offsets[t] = sh[t];
        g_cursor[t]  = sh[t];
    }
    if (t == 0) g_offsets[NUM_TYPES] = n;
}

__global__ void k_scatter(const void* __restrict__ types, int n) {
    const int is64 = g_is64;
    for (int i = blockIdx.x * blockDim.x + threadIdx.x; i < n;
         i += gridDim.x * blockDim.x) {
        int t = get_type(types, i, is64);
        int pos = atomicAdd(&g_cursor[t], 1);
        if (pos >= 0 && pos < MAX_N) g_perm[pos] = i;
    }
}

// ---------------------------------------------------------------------------
// Pass 2: per-type GEMM. Block = 256 threads = 8 warps, tile = 128 rows x 64.
// grid = (16 tile-slots, 64 types); slot strides over tiles of its segment.
// Each warp: m16 rows x n64 x k64 via 8x8 mma.m16n8k8 tf32.
// ---------------------------------------------------------------------------
#define WSTR 68

__global__ void __launch_bounds__(256, 2)
k_gemm(const float* __restrict__ x, const float* __restrict__ Wm,
       const float* __restrict__ bias, float* __restrict__ out) {
    __shared__ float Ws[64][WSTR];
    __shared__ float bs[64];

    const int type = blockIdx.y;
    const int seg0 = g_offsets[type];
    const int count = g_offsets[type + 1] - seg0;
    if (count == 0) return;

    // Stage W[type] (64x64) into smem, pre-converted to tf32 bits.
    const float* Wt = Wm + type * 4096;
    for (int i = threadIdx.x; i < 4096; i += 256) {
        int k = i >> 6, n = i & 63;
        Ws[k][n] = __uint_as_float(f2tf32(Wt[i]));
    }
    if (threadIdx.x < 64) bs[threadIdx.x] = bias[type * 64 + threadIdx.x];
    __syncthreads();

    const int warp = threadIdx.x >> 5;
    const int lane = threadIdx.x & 31;
    const int g  = lane >> 2;   // groupID: A-row within m16 / B-col within n8
    const int tg = lane & 3;    // thread-in-group: k index base

    for (int tile = blockIdx.x; tile * 128 < count; tile += gridDim.x) {
        const int lr0 = tile * 128 + warp * 16 + g;
        const int lr1 = lr0 + 8;
        const int row0 = (lr0 < count) ? g_perm[seg0 + lr0] : -1;
        const int row1 = (lr1 < count) ? g_perm[seg0 + lr1] : -1;

        const float* x0 = x + (row0 >= 0 ? (size_t)row0 * 64 : 0);
        const float* x1 = x + (row1 >= 0 ? (size_t)row1 * 64 : 0);
        uint32_t A[8][4];
#pragma unroll
        for (int ks = 0; ks < 8; ks++) {
            int c = ks * 8 + tg;
            float a0 = (row0 >= 0) ? __ldg(&x0[c])     : 0.f;
            float a1 = (row1 >= 0) ? __ldg(&x1[c])     : 0.f;
            float a2 = (row0 >= 0) ? __ldg(&x0[c + 4]) : 0.f;
            float a3 = (row1 >= 0) ? __ldg(&x1[c + 4]) : 0.f;
            A[ks][0] = f2tf32(a0);
            A[ks][1] = f2tf32(a1);
            A[ks][2] = f2tf32(a2);
            A[ks][3] = f2tf32(a3);
        }

        float acc[8][4];
#pragma unroll
        for (int nc = 0; nc < 8; nc++) {
            acc[nc][0] = 0.f; acc[nc][1] = 0.f;
            acc[nc][2] = 0.f; acc[nc][3] = 0.f;
        }

#pragma unroll
        for (int ks = 0; ks < 8; ks++) {
#pragma unroll
            for (int nc = 0; nc < 8; nc++) {
                uint32_t b0 = __float_as_uint(Ws[ks * 8 + tg    ][nc * 8 + g]);
                uint32_t b1 = __float_as_uint(Ws[ks * 8 + tg + 4][nc * 8 + g]);
                mma_tf32(acc[nc], A[ks], b0, b1);
            }
        }

#pragma unroll
        for (int nc = 0; nc < 8; nc++) {
            int col = nc * 8 + tg * 2;
            float bv0 = bs[col], bv1 = bs[col + 1];
            if (row0 >= 0) {
                float2 v = make_float2(acc[nc][0] + bv0, acc[nc][1] + bv1);
                *reinterpret_cast<float2*>(out + (size_t)row0 * 64 + col) = v;
            }
            if (row1 >= 0) {
                float2 v = make_float2(acc[nc][2] + bv0, acc[nc][3] + bv1);
                *reinterpret_cast<float2*>(out + (size_t)row1 * 64 + col) = v;
            }
        }
    }
}

// ---------------------------------------------------------------------------
extern "C" void kernel_launch(void* const* d_in, const int* in_sizes, int n_in,
                              void* d_out, int out_size) {
    const float* x      = (const float*)d_in[0];
    const void*  types  = d_in[1];
    const float* matrix = (const float*)d_in[2];
    const float* bias   = (const float*)d_in[3];
    float*       out    = (float*)d_out;
    const int n = in_sizes[1];  // number of rows

    k_detect<<<1, 1>>>((const int*)types, n);
    k_zero<<<1, 64>>>();
    k_hist<<<296, 256>>>(types, n);
    k_scan<<<1, 64>>>(n);
    k_scatter<<<296, 256>>>(types, n);

    dim3 grid(16, NUM_TYPES);
    k_gemm<<<grid, 256>>>(x, matrix, bias, out);
}

// round 3
// speedup vs baseline: 1.7551x; 1.7551x over previous
#include <cuda_runtime.h>
#include <cuda_bf16.h>
#include <cstdint>

// AtomTypeLinear: out[n,:] = x[n,:] @ M[type[n]] + b[type[n]]
// N=100000, IN=OUT=64, NUM_TYPES=64, fp32.
//
// 3-kernel pipeline:
//   k_hist:    per-block type histograms (no atomics) + inline dtype detect
//   k_scatter: each block derives its per-type cursors from all partials
//              (no global atomics), builds g_perm; block 0 writes g_offsets
//   k_gemm:    per-type tiled GEMM, mma.sync.m16n8k8 tf32, W in smem

#define NUM_TYPES 64
#define MAX_N     102400
#define NB        128     // histogram / scatter blocks

__device__ int g_partial[NB][NUM_TYPES];
__device__ int g_offsets[NUM_TYPES + 1];
__device__ int g_perm[MAX_N];
__device__ int g_is64;

// ---------------------------------------------------------------------------
__device__ __forceinline__ int get_type(const void* types, int i, int is64) {
    int t = is64 ? (int)((const long long*)types)[i]
                 : ((const int*)types)[i];
    return (t >= 0 && t < NUM_TYPES) ? t : 0;  // guard: fail on rel_err, not IMA
}

__device__ __forceinline__ uint32_t f2tf32(float f) {
    uint32_t r;
    asm("cvt.rna.tf32.f32 %0, %1;" : "=r"(r) : "f"(f));
    return r;
}

__device__ __forceinline__ void mma_tf32(float* c, const uint32_t* a,
                                         uint32_t b0, uint32_t b1) {
    asm volatile(
        "mma.sync.aligned.m16n8k8.row.col.f32.tf32.tf32.f32 "
        "{%0,%1,%2,%3}, {%4,%5,%6,%7}, {%8,%9}, {%0,%1,%2,%3};"
        : "+f"(c[0]), "+f"(c[1]), "+f"(c[2]), "+f"(c[3])
        : "r"(a[0]), "r"(a[1]), "r"(a[2]), "r"(a[3]), "r"(b0), "r"(b1));
}

// ---------------------------------------------------------------------------
// Kernel 1: per-block histogram + dtype detect.
// dtype detect: values in [0,64); int64 (LE) => every odd 32-bit word is 0.
// Reads only words [0,128) -> in-bounds under either interpretation (n>=128).
// ---------------------------------------------------------------------------
__global__ void __launch_bounds__(256)
k_hist(const void* __restrict__ types, int n) {
    __shared__ int sh[NUM_TYPES];
    __shared__ int s_is64;
    if (threadIdx.x < NUM_TYPES) sh[threadIdx.x] = 0;
    if (threadIdx.x == 0) s_is64 = 1;
    __syncthreads();
    if (threadIdx.x < 64) {
        int idx = 2 * threadIdx.x + 1;
        if (idx < n && ((const int*)types)[idx] != 0) s_is64 = 0;
    }
    __syncthreads();
    const int is64 = s_is64;
    if (blockIdx.x == 0 && threadIdx.x == 0) g_is64 = is64;

    const int chunk = (n + NB - 1) / NB;
    const int lo = blockIdx.x * chunk;
    const int hi = min(n, lo + chunk);
    for (int i = lo + threadIdx.x; i < hi; i += 256)
        atomicAdd(&sh[get_type(types, i, is64)], 1);
    __syncthreads();
    if (threadIdx.x < NUM_TYPES)
        g_partial[blockIdx.x][threadIdx.x] = sh[threadIdx.x];
}

// ---------------------------------------------------------------------------
// Kernel 2: scatter. Each block reconstructs the (type, block) scan locally,
// then fills its chunk of g_perm with only shared-memory atomics.
// ---------------------------------------------------------------------------
__global__ void __launch_bounds__(256)
k_scatter(const void* __restrict__ types, int n) {
    __shared__ int s_total[NUM_TYPES];
    __shared__ int s_before[NUM_TYPES];
    __shared__ int s_off[NUM_TYPES];
    __shared__ int s_cursor[NUM_TYPES];

    const int is64 = g_is64;
    const int b = blockIdx.x;

    if (threadIdx.x < NUM_TYPES) {
        int before = 0, total = 0;
        for (int bb = 0; bb < NB; bb++) {
            int c = g_partial[bb][threadIdx.x];
            if (bb < b) before += c;
            total += c;
        }
        s_total[threadIdx.x]  = total;
        s_before[threadIdx.x] = before;
    }
    __syncthreads();
    if (threadIdx.x == 0) {
        int acc = 0;
        for (int t = 0; t < NUM_TYPES; t++) {
            s_off[t] = acc;
            acc += s_total[t];
        }
    }
    __syncthreads();
    if (threadIdx.x < NUM_TYPES) {
        s_cursor[threadIdx.x] = s_off[threadIdx.x] + s_before[threadIdx.x];
        if (b == 0) g_offsets[threadIdx.x] = s_off[threadIdx.x];
    }
    if (b == 0 && threadIdx.x == 0) g_offsets[NUM_TYPES] = n;
    __syncthreads();

    const int chunk = (n + NB - 1) / NB;
    const int lo = b * chunk;
    const int hi = min(n, lo + chunk);
    for (int i = lo + threadIdx.x; i < hi; i += 256) {
        int t = get_type(types, i, is64);
        int pos = atomicAdd(&s_cursor[t], 1);
        if (pos >= 0 && pos < MAX_N) g_perm[pos] = i;
    }
}

// ---------------------------------------------------------------------------
// Kernel 3: per-type GEMM. Block = 8 warps, tile = 128 rows x 64 cols, K=64.
// grid = (16 tile-slots, 64 types), slot strides over its segment's tiles.
// A-fragments software-pipelined per k-step to keep regs low (3 blocks/SM).
// ---------------------------------------------------------------------------
#define WSTR 68

__global__ void __launch_bounds__(256, 3)
k_gemm(const float* __restrict__ x, const float* __restrict__ Wm,
       const float* __restrict__ bias, float* __restrict__ out) {
    __shared__ float Ws[64][WSTR];
    __shared__ float bs[64];

    const int type = blockIdx.y;
    const int seg0 = g_offsets[type];
    const int count = g_offsets[type + 1] - seg0;
    if (count == 0) return;

    const float* Wt = Wm + type * 4096;
    for (int i = threadIdx.x; i < 4096; i += 256) {
        int k = i >> 6, nn = i & 63;
        Ws[k][nn] = __uint_as_float(f2tf32(Wt[i]));
    }
    if (threadIdx.x < 64) bs[threadIdx.x] = bias[type * 64 + threadIdx.x];
    __syncthreads();

    const int warp = threadIdx.x >> 5;
    const int lane = threadIdx.x & 31;
    const int g  = lane >> 2;   // A-row within m16 / B-col within n8
    const int tg = lane & 3;

    for (int tile = blockIdx.x; tile * 128 < count; tile += gridDim.x) {
        const int lr0 = tile * 128 + warp * 16 + g;
        const int lr1 = lr0 + 8;
        const int row0 = (lr0 < count) ? g_perm[seg0 + lr0] : -1;
        const int row1 = (lr1 < count) ? g_perm[seg0 + lr1] : -1;
        const float* x0 = x + (row0 >= 0 ? (size_t)row0 * 64 : 0);
        const float* x1 = x + (row1 >= 0 ? (size_t)row1 * 64 : 0);
        const bool v0 = (row0 >= 0), v1 = (row1 >= 0);

        float acc[8][4];
#pragma unroll
        for (int nc = 0; nc < 8; nc++) {
            acc[nc][0] = 0.f; acc[nc][1] = 0.f;
            acc[nc][2] = 0.f; acc[nc][3] = 0.f;
        }

        // 2-stage pipelined A-fragment loads (8 regs instead of 32)
        uint32_t Acur[4], Anxt[4];
        {
            int c = tg;
            Acur[0] = f2tf32(v0 ? __ldg(&x0[c])     : 0.f);
            Acur[1] = f2tf32(v1 ? __ldg(&x1[c])     : 0.f);
            Acur[2] = f2tf32(v0 ? __ldg(&x0[c + 4]) : 0.f);
            Acur[3] = f2tf32(v1 ? __ldg(&x1[c + 4]) : 0.f);
        }
#pragma unroll
        for (int ks = 0; ks < 8; ks++) {
            if (ks < 7) {
                int c = (ks + 1) * 8 + tg;
                Anxt[0] = f2tf32(v0 ? __ldg(&x0[c])     : 0.f);
                Anxt[1] = f2tf32(v1 ? __ldg(&x1[c])     : 0.f);
                Anxt[2] = f2tf32(v0 ? __ldg(&x0[c + 4]) : 0.f);
                Anxt[3] = f2tf32(v1 ? __ldg(&x1[c + 4]) : 0.f);
            }
#pragma unroll
            for (int nc = 0; nc < 8; nc++) {
                uint32_t b0 = __float_as_uint(Ws[ks * 8 + tg    ][nc * 8 + g]);
                uint32_t b1 = __float_as_uint(Ws[ks * 8 + tg + 4][nc * 8 + g]);
                mma_tf32(acc[nc], Acur, b0, b1);
            }
#pragma unroll
            for (int j = 0; j < 4; j++) Acur[j] = Anxt[j];
        }

#pragma unroll
        for (int nc = 0; nc < 8; nc++) {
            int col = nc * 8 + tg * 2;
            float bv0 = bs[col], bv1 = bs[col + 1];
            if (v0) {
                float2 v = make_float2(acc[nc][0] + bv0, acc[nc][1] + bv1);
                *reinterpret_cast<float2*>(out + (size_t)row0 * 64 + col) = v;
            }
            if (v1) {
                float2 v = make_float2(acc[nc][2] + bv0, acc[nc][3] + bv1);
                *reinterpret_cast<float2*>(out + (size_t)row1 * 64 + col) = v;
            }
        }
    }
}

// ---------------------------------------------------------------------------
extern "C" void kernel_launch(void* const* d_in, const int* in_sizes, int n_in,
                              void* d_out, int out_size) {
    const float* x      = (const float*)d_in[0];
    const void*  types  = d_in[1];
    const float* matrix = (const float*)d_in[2];
    const float* bias   = (const float*)d_in[3];
    float*       out    = (float*)d_out;
    const int n = in_sizes[1];

    k_hist<<<NB, 256>>>(types, n);
    k_scatter<<<NB, 256>>>(types, n);
    dim3 grid(16, NUM_TYPES);
    k_gemm<<<grid, 256>>>(x, matrix, bias, out);
}